// round 14
// baseline (speedup 1.0000x reference)
#include <cuda_runtime.h>
#include <cuda_bf16.h>
#include <cstdint>

#define Bb 4
#define Ss 1024
#define Dd 512
#define Hh 8
#define DH 64
#define RR 2047
#define RPAD 2304

__device__ __nv_bfloat16 g_wqh[512*512], g_wql[512*512];
__device__ __nv_bfloat16 g_wkh[512*512], g_wkl[512*512];
__device__ __nv_bfloat16 g_wvh[512*512], g_wvl[512*512];
__device__ __nv_bfloat16 g_woh[512*512], g_wol[512*512];
__device__ __nv_bfloat16 g_qh[32*1024*64], g_ql[32*1024*64];
__device__ __nv_bfloat16 g_kh[32*1024*64], g_kl[32*1024*64];
__device__ __nv_bfloat16 g_vh[32*1024*64], g_vl[32*1024*64];
__device__ __nv_bfloat16 g_relh[RPAD*64], g_rell[RPAD*64];
__device__ __nv_bfloat16 g_ctxh[4096*512], g_ctxl[4096*512];
__device__ float         g_rowsum[32*1024];

extern __shared__ char dsm[];

__device__ __forceinline__ uint32_t smem_u32(const void* p) {
    uint32_t a;
    asm("{ .reg .u64 t; cvta.to.shared.u64 t, %1; cvt.u32.u64 %0, t; }" : "=r"(a) : "l"(p));
    return a;
}
__device__ __forceinline__ void ldsm4(uint32_t* r, uint32_t a) {
    asm volatile("ldmatrix.sync.aligned.m8n8.x4.shared.b16 {%0,%1,%2,%3}, [%4];"
        : "=r"(r[0]), "=r"(r[1]), "=r"(r[2]), "=r"(r[3]) : "r"(a));
}
__device__ __forceinline__ void ldsm4t(uint32_t* r, uint32_t a) {
    asm volatile("ldmatrix.sync.aligned.m8n8.x4.trans.shared.b16 {%0,%1,%2,%3}, [%4];"
        : "=r"(r[0]), "=r"(r[1]), "=r"(r[2]), "=r"(r[3]) : "r"(a));
}
__device__ __forceinline__ void mma16816(float* d, const uint32_t* a, const uint32_t* b) {
    asm volatile("mma.sync.aligned.m16n8k16.row.col.f32.bf16.bf16.f32 "
        "{%0,%1,%2,%3}, {%4,%5,%6,%7}, {%8,%9}, {%0,%1,%2,%3};"
        : "+f"(d[0]), "+f"(d[1]), "+f"(d[2]), "+f"(d[3])
        : "r"(a[0]), "r"(a[1]), "r"(a[2]), "r"(a[3]), "r"(b[0]), "r"(b[1]));
}
__device__ __forceinline__ void cp16(uint32_t dst, const void* src) {
    asm volatile("cp.async.cg.shared.global [%0], [%1], 16;" :: "r"(dst), "l"(src));
}
#define CP_COMMIT() asm volatile("cp.async.commit_group;" ::: "memory")
#define CP_WAIT(N)  asm volatile("cp.async.wait_group %0;" :: "n"(N) : "memory")

__device__ __forceinline__ uint32_t pack_split(float a, float b, float& ra, float& rb) {
    __nv_bfloat16 ha = __float2bfloat16_rn(a), hb = __float2bfloat16_rn(b);
    ra = a - __bfloat162float(ha);
    rb = b - __bfloat162float(hb);
    return (uint32_t)__bfloat16_as_ushort(ha) | ((uint32_t)__bfloat16_as_ushort(hb) << 16);
}
__device__ __forceinline__ uint32_t pack_bf2(float a, float b) {
    return (uint32_t)__bfloat16_as_ushort(__float2bfloat16_rn(a)) |
           ((uint32_t)__bfloat16_as_ushort(__float2bfloat16_rn(b)) << 16);
}

// ---------- weights-only fp32 -> bf16 hi/lo split (one launch) ------------
__global__ __launch_bounds__(256)
void split_w(const float* Wq, const float* Wk, const float* Wv, const float* Wo,
             __nv_bfloat16* wqh, __nv_bfloat16* wql, __nv_bfloat16* wkh, __nv_bfloat16* wkl,
             __nv_bfloat16* wvh, __nv_bfloat16* wvl, __nv_bfloat16* woh, __nv_bfloat16* wol) {
    int gb = blockIdx.x;
    int w = gb >> 8, i = (gb & 255) * 256 + threadIdx.x;
    const float* in = w == 0 ? Wq : w == 1 ? Wk : w == 2 ? Wv : Wo;
    __nv_bfloat16* oh = w == 0 ? wqh : w == 1 ? wkh : w == 2 ? wvh : woh;
    __nv_bfloat16* ol = w == 0 ? wql : w == 1 ? wkl : w == 2 ? wvl : wol;
    float4 val = reinterpret_cast<const float4*>(in)[i];
    float r0, r1, r2, r3;
    uint32_t h0 = pack_split(val.x, val.y, r0, r1);
    uint32_t h1 = pack_split(val.z, val.w, r2, r3);
    reinterpret_cast<uint2*>(oh)[i] = make_uint2(h0, h1);
    reinterpret_cast<uint2*>(ol)[i] = make_uint2(pack_bf2(r0, r1), pack_bf2(r2, r3));
}

// ---- shared 48-MMA step, per-j B loads (low register pressure) -----------
__device__ __forceinline__ void mma_step48(float acc[2][8][4], uint32_t aBase, uint32_t bBase,
                                           uint32_t a_off, uint32_t a_sw, uint32_t a_cb,
                                           uint32_t b_off, uint32_t b_sw, uint32_t b_cb) {
    #pragma unroll
    for (int k = 0; k < 4; k++) {
        uint32_t aA = aBase + a_off + (((uint32_t)(k * 32) + a_cb) ^ a_sw);
        uint32_t ah0[4], ah1[4], al0[4], al1[4];
        ldsm4(ah0, aA); ldsm4(ah1, aA + 2048);
        ldsm4(al0, aA + 16384); ldsm4(al1, aA + 16384 + 2048);
        uint32_t bA = bBase + b_off + (((uint32_t)(k * 32) + b_cb) ^ b_sw);
        #pragma unroll
        for (int j = 0; j < 4; j++) {
            uint32_t bh[4], bl[4];
            ldsm4(bh, bA + j * 2048); ldsm4(bl, bA + 16384 + j * 2048);
            mma16816(acc[0][2*j],   ah0, &bh[0]); mma16816(acc[0][2*j+1], ah0, &bh[2]);
            mma16816(acc[1][2*j],   ah1, &bh[0]); mma16816(acc[1][2*j+1], ah1, &bh[2]);
            mma16816(acc[0][2*j],   ah0, &bl[0]); mma16816(acc[0][2*j+1], ah0, &bl[2]);
            mma16816(acc[1][2*j],   ah1, &bl[0]); mma16816(acc[1][2*j+1], ah1, &bl[2]);
            mma16816(acc[0][2*j],   al0, &bh[0]); mma16816(acc[0][2*j+1], al0, &bh[2]);
            mma16816(acc[1][2*j],   al1, &bh[0]); mma16816(acc[1][2*j+1], al1, &bh[2]);
        }
    }
}

// ====== K-chunked 128x128 GEMM, bf16 hi/lo A and B (outproj) ==============
__device__ __forceinline__ void mma_core_128(
    float acc[2][8][4],
    const __nv_bfloat16* Ah, const __nv_bfloat16* Al, int lda,
    const __nv_bfloat16* Bh, const __nv_bfloat16* Bl, int ldb, int kchunks)
{
    const uint32_t sb = smem_u32(dsm);
    int tid = threadIdx.x, lane = tid & 31, wid = tid >> 5;
    int wm = (wid & 3) << 5, wn = (wid >> 2) << 6;
    uint32_t a_row = wm + (lane & 15);
    uint32_t a_off = a_row * 128, a_sw = (a_row & 7) << 4, a_cb = lane & 16;
    uint32_t b_row = wn + (lane & 7) + ((lane >> 1) & 8);
    uint32_t b_off = b_row * 128, b_sw = (b_row & 7) << 4, b_cb = (lane & 8) << 1;

    auto issue = [&](int kc, int stage) {
        uint32_t s0 = sb + stage * 65536u;
        #pragma unroll
        for (int l = 0; l < 4; l++) {
            int i = tid + l * 256, r = i >> 3, c = i & 7;
            uint32_t doff = r * 128 + ((c * 16) ^ ((r & 7) << 4));
            size_t ga = (size_t)r * lda + kc * 64 + c * 8;
            size_t gb = (size_t)r * ldb + kc * 64 + c * 8;
            cp16(s0 + doff, Ah + ga); cp16(s0 + 16384 + doff, Al + ga);
            cp16(s0 + 32768 + doff, Bh + gb); cp16(s0 + 49152 + doff, Bl + gb);
        }
        CP_COMMIT();
    };

    issue(0, 0);
    for (int kc = 0; kc < kchunks; kc++) {
        if (kc + 1 < kchunks) { issue(kc + 1, (kc + 1) & 1); CP_WAIT(1); }
        else CP_WAIT(0);
        __syncthreads();
        uint32_t base = sb + (kc & 1) * 65536u;
        mma_step48(acc, base, base + 32768, a_off, a_sw, a_cb, b_off, b_sw, b_cb);
        if (kc + 1 < kchunks) __syncthreads();
    }
}

// ===== MEGA scores: 128-row blocks, 512 threads, 4x4 warp grid ===========
#define PS_OFF 65536
#define RS_OFF (PS_OFF + 133120)
#define SMEM_SCORES (RS_OFF + 64)

__global__ __launch_bounds__(512)
void scores_fused(const __nv_bfloat16* qh_g, const __nv_bfloat16* ql_g,
                  const __nv_bfloat16* kh_g, const __nv_bfloat16* kl_g,
                  const __nv_bfloat16* relh, const __nv_bfloat16* rell,
                  float* __restrict__ csc, float* __restrict__ psc,
                  float* __restrict__ eb, float* __restrict__ rowsum_g)
{
    const uint32_t sb = smem_u32(dsm);
    float* p_sh = reinterpret_cast<float*>(dsm + PS_OFF);     // [128][260]
    int tid = threadIdx.x, lane = tid & 31, wid = tid >> 5;
    int wm = (wid & 3) << 5, wn = (wid >> 2) << 5;            // 4x4 grid, 32x32 tiles
    int sblk = blockIdx.x, bh = blockIdx.y, s0 = sblk << 7;

    uint32_t a_row = wm + (lane & 15);
    uint32_t a_off = a_row * 128, a_sw = (a_row & 7) << 4, a_cb = lane & 16;
    uint32_t b_row = wn + (lane & 7) + ((lane >> 1) & 8);
    uint32_t b_off = b_row * 128, b_sw = (b_row & 7) << 4, b_cb = (lane & 8) << 1;

    const __nv_bfloat16* qhb = qh_g + ((size_t)bh * Ss + s0) * DH;
    const __nv_bfloat16* qlb = ql_g + ((size_t)bh * Ss + s0) * DH;
    const __nv_bfloat16* khb = kh_g + (size_t)bh * Ss * DH;
    const __nv_bfloat16* klb = kl_g + (size_t)bh * Ss * DH;

    #pragma unroll
    for (int l = 0; l < 2; l++) {
        int i = tid + l * 512, r = i >> 3, c = i & 7;
        uint32_t doff = r * 128 + ((c * 16) ^ ((r & 7) << 4));
        cp16(sb + doff, qhb + (size_t)r * 64 + c * 8);
        cp16(sb + 16384 + doff, qlb + (size_t)r * 64 + c * 8);
    }
    auto loadB = [&](const __nv_bfloat16* BH, const __nv_bfloat16* BL) {
        #pragma unroll
        for (int l = 0; l < 2; l++) {
            int i = tid + l * 512, r = i >> 3, c = i & 7;
            uint32_t doff = r * 128 + ((c * 16) ^ ((r & 7) << 4));
            cp16(sb + 32768 + doff, BH + (size_t)r * 64 + c * 8);
            cp16(sb + 49152 + doff, BL + (size_t)r * 64 + c * 8);
        }
        CP_COMMIT();
    };

    float acc[2][4][4];
    auto gemm = [&]() {
        #pragma unroll
        for (int mi = 0; mi < 2; mi++)
            #pragma unroll
            for (int jj = 0; jj < 4; jj++)
                #pragma unroll
                for (int x = 0; x < 4; x++) acc[mi][jj][x] = 0.f;
        #pragma unroll
        for (int k = 0; k < 4; k++) {
            uint32_t aA = sb + a_off + (((uint32_t)(k * 32) + a_cb) ^ a_sw);
            uint32_t ah0[4], ah1[4], al0[4], al1[4];
            ldsm4(ah0, aA); ldsm4(ah1, aA + 2048);
            ldsm4(al0, aA + 16384); ldsm4(al1, aA + 16384 + 2048);
            uint32_t bA = sb + 32768 + b_off + (((uint32_t)(k * 32) + b_cb) ^ b_sw);
            #pragma unroll
            for (int jb = 0; jb < 2; jb++) {
                uint32_t bh4[4], bl4[4];
                ldsm4(bh4, bA + jb * 2048);
                ldsm4(bl4, bA + 16384 + jb * 2048);
                #pragma unroll
                for (int h = 0; h < 2; h++) {
                    int jj = jb * 2 + h;
                    mma16816(acc[0][jj], ah0, &bh4[2*h]); mma16816(acc[1][jj], ah1, &bh4[2*h]);
                    mma16816(acc[0][jj], ah0, &bl4[2*h]); mma16816(acc[1][jj], ah1, &bl4[2*h]);
                    mma16816(acc[0][jj], al0, &bh4[2*h]); mma16816(acc[1][jj], al1, &bh4[2*h]);
                }
            }
        }
    };

    int er_ = wm + (lane >> 2), ec_ = wn + ((lane & 3) << 1);

    auto scatter = [&](int ju) {
        #pragma unroll
        for (int mi = 0; mi < 2; mi++)
            #pragma unroll
            for (int jj = 0; jj < 4; jj++) {
                int u = ju * 128 + ec_ + jj * 8;
                #pragma unroll
                for (int hf = 0; hf < 2; hf++) {
                    int r = er_ + mi * 16 + hf * 8;
                    int t = u + r - 127;
                    if ((unsigned)t < 1024u)       p_sh[r * 260 + (t & 255)] = acc[mi][jj][hf * 2];
                    if ((unsigned)(t + 1) < 1024u) p_sh[r * 260 + ((t + 1) & 255)] = acc[mi][jj][hf * 2 + 1];
                }
            }
    };

    int relbase = 896 - s0;
    loadB(relh + (size_t)relbase * 64, rell + (size_t)relbase * 64);
    CP_WAIT(0); __syncthreads();
    gemm();                                     // pos u-tile 0
    __syncthreads();
    loadB(relh + (size_t)(relbase + 128) * 64, rell + (size_t)(relbase + 128) * 64);
    scatter(0);
    CP_WAIT(0); __syncthreads();

    const float scl = 0.04419417382415922f;
    size_t prow = (size_t)bh * Ss + s0;
    float rs[4] = {0.f, 0.f, 0.f, 0.f};

    for (int j = 0; j < 8; j++) {
        gemm();                                 // pos u-tile j+1
        __syncthreads();
        loadB(khb + (size_t)(j * 128) * 64, klb + (size_t)(j * 128) * 64);
        scatter(j + 1);
        CP_WAIT(0); __syncthreads();
        gemm();                                 // content tile j
        __syncthreads();                        // B consumed
        if (j < 7) {
            int rb = relbase + (j + 2) * 128;
            loadB(relh + (size_t)rb * 64, rell + (size_t)rb * 64);   // overlap epilogue
        }
        #pragma unroll
        for (int l = 0; l < 8; l++) {           // coalesced psc tile write
            int i = tid + l * 512, r = i >> 5, c4 = i & 31;
            float4 v = *reinterpret_cast<float4*>(&p_sh[r * 260 + ((j & 1) * 128) + c4 * 4]);
            *reinterpret_cast<float4*>(&psc[(prow + r) * Ss + j * 128 + c4 * 4]) = v;
        }
        #pragma unroll
        for (int mi = 0; mi < 2; mi++)
            #pragma unroll
            for (int jj = 0; jj < 4; jj++) {
                int tb = j * 128 + ec_ + jj * 8;
                int sc = (j & 1) * 128 + ((ec_ + jj * 8) & 127);
                int r0 = er_ + mi * 16, r1 = r0 + 8;
                float2 p0 = *reinterpret_cast<float2*>(&p_sh[r0 * 260 + sc]);
                float2 p1 = *reinterpret_cast<float2*>(&p_sh[r1 * 260 + sc]);
                float c0 = acc[mi][jj][0], c1 = acc[mi][jj][1];
                float c2 = acc[mi][jj][2], c3 = acc[mi][jj][3];
                size_t o0 = (prow + r0) * Ss + tb, o1 = (prow + r1) * Ss + tb;
                *reinterpret_cast<float2*>(&csc[o0]) = make_float2(c0, c1);
                *reinterpret_cast<float2*>(&csc[o1]) = make_float2(c2, c3);
                float e00 = __expf((c0 + p0.x) * scl), e01 = __expf((c1 + p0.y) * scl);
                float e10 = __expf((c2 + p1.x) * scl), e11 = __expf((c3 + p1.y) * scl);
                *reinterpret_cast<float2*>(&eb[o0]) = make_float2(e00, e01);
                *reinterpret_cast<float2*>(&eb[o1]) = make_float2(e10, e11);
                rs[mi * 2 + 0] += e00 + e01;
                rs[mi * 2 + 1] += e10 + e11;
            }
        CP_WAIT(0); __syncthreads();
    }

    #pragma unroll
    for (int i = 0; i < 4; i++) {
        rs[i] += __shfl_xor_sync(~0u, rs[i], 1);
        rs[i] += __shfl_xor_sync(~0u, rs[i], 2);
    }
    float* rsh = reinterpret_cast<float*>(dsm + 32768);   // [4 groups][128]
    if ((lane & 3) == 0) {
        int g = wid >> 2;
        rsh[g * 128 + er_]      = rs[0];
        rsh[g * 128 + er_ + 8]  = rs[1];
        rsh[g * 128 + er_ + 16] = rs[2];
        rsh[g * 128 + er_ + 24] = rs[3];
    }
    __syncthreads();
    if (tid < 128)
        rowsum_g[prow + tid] = (rsh[tid] + rsh[128 + tid]) + (rsh[256 + tid] + rsh[384 + tid]);
}

// ------ q/k/v projection: reads fp32 input directly, converts in-kernel ---
// smem: A hi 0(16K), A lo 16384(16K); B ring at 32768: 2 x (hi 16K + lo 16K)
#define PROJ_SMEM 98304

__global__ __launch_bounds__(256)
void proj_qkv_mma(const float* xq, const float* xk, const float* xv,
                  const __nv_bfloat16* wqh, const __nv_bfloat16* wql,
                  const __nv_bfloat16* wkh, const __nv_bfloat16* wkl,
                  const __nv_bfloat16* wvh, const __nv_bfloat16* wvl,
                  const float* bq, const float* bk, const float* bv,
                  __nv_bfloat16* qh, __nv_bfloat16* ql, __nv_bfloat16* kh,
                  __nv_bfloat16* kl, __nv_bfloat16* vh, __nv_bfloat16* vl) {
    int z = blockIdx.z;
    const float* x = z == 0 ? xq : z == 1 ? xk : xv;
    const __nv_bfloat16* wh = z == 0 ? wqh : z == 1 ? wkh : wvh;
    const __nv_bfloat16* wl = z == 0 ? wql : z == 1 ? wkl : wvl;
    const float* bias = z == 0 ? bq : z == 1 ? bk : bv;
    __nv_bfloat16* oh = z == 0 ? qh : z == 1 ? kh : vh;
    __nv_bfloat16* ol = z == 0 ? ql : z == 1 ? kl : vl;

    char* sAh = dsm; char* sAl = dsm + 16384;
    const uint32_t sb = smem_u32(dsm);
    int n0 = blockIdx.x << 7, m0 = blockIdx.y << 7;
    const float* xb = x + (size_t)m0 * Dd;
    int tid = threadIdx.x, lane = tid & 31, wid = tid >> 5;
    int wm = (wid & 3) << 5, wn = (wid >> 2) << 6;
    uint32_t a_row = wm + (lane & 15);
    uint32_t a_off = a_row * 128, a_sw = (a_row & 7) << 4, a_cb = lane & 16;
    uint32_t b_row = wn + (lane & 7) + ((lane >> 1) & 8);
    uint32_t b_off = b_row * 128, b_sw = (b_row & 7) << 4, b_cb = (lane & 8) << 1;

    auto issueB = [&](int kc, int st) {
        uint32_t s0 = sb + 32768 + (uint32_t)st * 32768u;
        #pragma unroll
        for (int l = 0; l < 4; l++) {
            int i = tid + l * 256, r = i >> 3, c = i & 7;
            uint32_t doff = r * 128 + ((c * 16) ^ ((r & 7) << 4));
            size_t g = (size_t)(n0 + r) * Dd + kc * 64 + c * 8;
            cp16(s0 + doff, wh + g);
            cp16(s0 + 16384 + doff, wl + g);
        }
        CP_COMMIT();
    };

    float acc[2][8][4] = {};
    issueB(0, 0);
    for (int kc = 0; kc < 8; kc++) {
        if (kc + 1 < 8) issueB(kc + 1, (kc + 1) & 1);
        // fill A: load fp32, split to hi/lo, swizzled STS (overlaps B cp.async)
        #pragma unroll
        for (int l = 0; l < 8; l++) {
            int i = tid + l * 256, r = i >> 4, c = i & 15;   // 128 rows x 16 float4
            float4 v = *reinterpret_cast<const float4*>(xb + (size_t)r * Dd + kc * 64 + c * 4);
            float r0, r1, r2, r3;
            uint32_t h0 = pack_split(v.x, v.y, r0, r1);
            uint32_t h1 = pack_split(v.z, v.w, r2, r3);
            uint32_t doff = r * 128 + ((c * 8) ^ ((r & 7) << 4));
            *reinterpret_cast<uint2*>(sAh + doff) = make_uint2(h0, h1);
            *reinterpret_cast<uint2*>(sAl + doff) = make_uint2(pack_bf2(r0, r1), pack_bf2(r2, r3));
        }
        if (kc + 1 < 8) CP_WAIT(1); else CP_WAIT(0);
        __syncthreads();
        uint32_t bBase = sb + 32768 + (uint32_t)(kc & 1) * 32768u;
        mma_step48(acc, sb, bBase, a_off, a_sw, a_cb, b_off, b_sw, b_cb);
        if (kc + 1 < 8) __syncthreads();
    }

    int er = ((wid & 3) << 5) + (lane >> 2);
    int ec = ((wid >> 2) << 6) + ((lane & 3) << 1);
    #pragma unroll
    for (int mi = 0; mi < 2; mi++)
        #pragma unroll
        for (int j = 0; j < 8; j++) {
            int c = n0 + ec + j * 8;
            float b0 = bias[c], b1 = bias[c + 1];
            #pragma unroll
            for (int hf = 0; hf < 2; hf++) {
                int m = m0 + er + mi * 16 + hf * 8;
                float v0 = acc[mi][j][hf*2] + b0, v1 = acc[mi][j][hf*2+1] + b1;
                int b = m >> 10, s = m & 1023, h = c >> 6, d = c & 63;
                size_t off = ((size_t)((((b << 3) | h) << 10) | s)) * DH + d;
                float r0, r1;
                uint32_t hv = pack_split(v0, v1, r0, r1);
                *reinterpret_cast<uint32_t*>(&oh[off]) = hv;
                *reinterpret_cast<uint32_t*>(&ol[off]) = pack_bf2(r0, r1);
            }
        }
}

// ------ output projection (bf16 hi/lo A from ctx) --------------------------
__global__ __launch_bounds__(256)
void outproj_mma(const __nv_bfloat16* xh, const __nv_bfloat16* xl,
                 const __nv_bfloat16* wh, const __nv_bfloat16* wl,
                 const float* bias, float* __restrict__ out) {
    int n0 = blockIdx.x << 7, m0 = blockIdx.y << 7;
    float acc[2][8][4] = {};
    mma_core_128(acc, xh + (size_t)m0 * Dd, xl + (size_t)m0 * Dd, Dd,
                 wh + (size_t)n0 * Dd, wl + (size_t)n0 * Dd, Dd, 8);
    int lane = threadIdx.x & 31, wid = threadIdx.x >> 5;
    int er = ((wid & 3) << 5) + (lane >> 2);
    int ec = ((wid >> 2) << 6) + ((lane & 3) << 1);
    #pragma unroll
    for (int mi = 0; mi < 2; mi++)
        #pragma unroll
        for (int j = 0; j < 8; j++) {
            int c = n0 + ec + j * 8;
            float b0 = bias[c], b1 = bias[c + 1];
            int m = m0 + er + mi * 16;
            *reinterpret_cast<float2*>(&out[(size_t)m * Dd + c]) =
                make_float2(acc[mi][j][0] + b0, acc[mi][j][1] + b1);
            *reinterpret_cast<float2*>(&out[(size_t)(m + 8) * Dd + c]) =
                make_float2(acc[mi][j][2] + b0, acc[mi][j][3] + b1);
        }
}

// ---------------- rel projection ------------------------------------------
__global__ __launch_bounds__(256)
void rel_proj_kernel(const float* P, const float* Wp, const float* bp,
                     __nv_bfloat16* oh, __nv_bfloat16* ol) {
    __shared__ float sWT[64 * 64];
    __shared__ float sP[4][64];
    int tid = threadIdx.x;
    for (int i = tid; i < 4096; i += 256) sWT[(i & 63) * 64 + (i >> 6)] = Wp[i];
    int g = tid >> 6, d = tid & 63;
    int r = blockIdx.x * 4 + g;
    sP[g][d] = (r < RR) ? P[r * 64 + d] : 0.f;
    __syncthreads();
    float acc = bp[d];
    #pragma unroll 16
    for (int c = 0; c < 64; c++) acc += sP[g][c] * sWT[c * 64 + d];
    if (r < RR) {
        __nv_bfloat16 h = __float2bfloat16_rn(acc);
        oh[r * 64 + d] = h;
        ol[r * 64 + d] = __float2bfloat16_rn(acc - __bfloat162float(h));
    }
}

// ------ ctx: 512 threads, V double-buffered; normalizes e, rewrites attn --
#define CTX_SMEM 65536

__global__ __launch_bounds__(512)
void ctx_mma(float* __restrict__ attn, const __nv_bfloat16* vh, const __nv_bfloat16* vl,
             const float* __restrict__ rowsum_g, __nv_bfloat16* ch, __nv_bfloat16* cl) {
    char* sAh = dsm; char* sAl = dsm + 16384;
    const uint32_t sb = smem_u32(dsm);
    __shared__ float sinv[128];
    int bh = blockIdx.y, s0 = blockIdx.x << 7;
    float* ab = attn + ((size_t)bh * Ss + s0) * Ss;
    const __nv_bfloat16* vhb = vh + (size_t)bh * Ss * DH;
    const __nv_bfloat16* vlb = vl + (size_t)bh * Ss * DH;
    int tid = threadIdx.x, lane = tid & 31, wid = tid >> 5;
    int wm = (wid & 3) << 5, wn = (wid >> 2) << 4;       // 4x4 warps, 32x16 tiles

    if (tid < 128) sinv[tid] = 1.0f / rowsum_g[(size_t)bh * Ss + s0 + tid];
    __syncthreads();

    uint32_t a_row = wm + (lane & 15);
    uint32_t a_off = a_row * 128, a_sw = (a_row & 7) << 4, a_cb = lane & 16;
    uint32_t bt = (lane & 7) + (lane & 8);
    uint32_t vcb = (uint32_t)(wn * 2) + (lane & 16);

    auto loadV = [&](int kc) {
        uint32_t vb = sb + 32768 + (uint32_t)(kc & 1) * 16384;
        int r = tid >> 3, c = tid & 7;
        uint32_t doff = r * 128 + ((c * 16) ^ ((r & 7) << 4));
        size_t g = (size_t)(kc * 64 + r) * DH + c * 8;
        cp16(vb + doff, vhb + g);
        cp16(vb + 8192 + doff, vlb + g);
        CP_COMMIT();
    };

    loadV(0);
    float acc[2][2][4] = {};
    for (int kc = 0; kc < 16; kc++) {
        if (kc) __syncthreads();
        if (kc + 1 < 16) loadV(kc + 1);
        #pragma unroll
        for (int l = 0; l < 4; l++) {
            int i = tid + l * 512, r = i >> 4, c = i & 15;
            float iv = sinv[r];
            float* gp = ab + (size_t)r * Ss + kc * 64 + c * 4;
            float4 v = *reinterpret_cast<const float4*>(gp);
            v.x *= iv; v.y *= iv; v.z *= iv; v.w *= iv;
            *reinterpret_cast<float4*>(gp) = v;
            float r0, r1, r2, r3;
            uint32_t h0 = pack_split(v.x, v.y, r0, r1);
            uint32_t h1 = pack_split(v.z, v.w, r2, r3);
            uint32_t doff = r * 128 + ((c * 8) ^ ((r & 7) << 4));
            *reinterpret_cast<uint2*>(sAh + doff) = make_uint2(h0, h1);
            *reinterpret_cast<uint2*>(sAl + doff) = make_uint2(pack_bf2(r0, r1), pack_bf2(r2, r3));
        }
        if (kc + 1 < 16) CP_WAIT(1); else CP_WAIT(0);
        __syncthreads();
        uint32_t vb = sb + 32768 + (uint32_t)(kc & 1) * 16384;
        #pragma unroll
        for (int k = 0; k < 4; k++) {
            uint32_t aA = sb + a_off + (((uint32_t)(k * 32) + a_cb) ^ a_sw);
            uint32_t ah0[4], ah1[4], al0[4], al1[4];
            ldsm4(ah0, aA); ldsm4(ah1, aA + 2048);
            ldsm4(al0, aA + 16384); ldsm4(al1, aA + 16384 + 2048);
            uint32_t t = (uint32_t)(k * 16) + bt;
            uint32_t va = vb + t * 128 + (vcb ^ ((t & 7) << 4));
            uint32_t vhf[4], vlf[4];
            ldsm4t(vhf, va);
            ldsm4t(vlf, va + 8192);
            #pragma unroll
            for (int jj = 0; jj < 2; jj++) {
                const uint32_t* bhp = &vhf[jj * 2];
                const uint32_t* blp = &vlf[jj * 2];
                mma16816(acc[0][jj], ah0, bhp); mma16816(acc[1][jj], ah1, bhp);
                mma16816(acc[0][jj], ah0, blp); mma16816(acc[1][jj], ah1, blp);
                mma16816(acc[0][jj], al0, bhp); mma16816(acc[1][jj], al1, bhp);
            }
        }
    }
    int b = bh >> 3, h = bh & 7;
    int er = wm + (lane >> 2), ec = wn + ((lane & 3) << 1);
    #pragma unroll
    for (int mi = 0; mi < 2; mi++)
        #pragma unroll
        for (int jj = 0; jj < 2; jj++)
            #pragma unroll
            for (int hf = 0; hf < 2; hf++) {
                int s = s0 + er + mi * 16 + hf * 8;
                int d = ec + jj * 8;
                size_t off = ((size_t)((b << 10) | s)) * Dd + (h << 6) + d;
                float r0, r1;
                uint32_t hv = pack_split(acc[mi][jj][hf*2], acc[mi][jj][hf*2+1], r0, r1);
                *reinterpret_cast<uint32_t*>(&ch[off]) = hv;
                *reinterpret_cast<uint32_t*>(&cl[off]) = pack_bf2(r0, r1);
            }
}

// -------------------------------------------------------------------------
extern "C" void kernel_launch(void* const* d_in, const int* in_sizes, int n_in,
                              void* d_out, int out_size) {
    const float* query   = (const float*)d_in[0];
    const float* key     = (const float*)d_in[1];
    const float* value   = (const float*)d_in[2];
    const float* pos_emb = (const float*)d_in[3];
    const float *Wq = (const float*)d_in[4],  *bq = (const float*)d_in[5];
    const float *Wk = (const float*)d_in[6],  *bk = (const float*)d_in[7];
    const float *Wv = (const float*)d_in[8],  *bv = (const float*)d_in[9];
    const float *Wo = (const float*)d_in[10], *bo = (const float*)d_in[11];
    const float *Wp = (const float*)d_in[12], *bp = (const float*)d_in[13];

    float* out  = (float*)d_out;
    float* attn = out  + (size_t)Bb * Ss * Dd;
    float* csc  = attn + (size_t)Bb * Hh * Ss * Ss;
    float* psc  = csc  + (size_t)Bb * Hh * Ss * Ss;

    __nv_bfloat16 *wqh, *wql, *wkh, *wkl, *wvh, *wvl, *woh, *wol;
    __nv_bfloat16 *qh, *ql, *kh, *kl, *vh, *vl, *relh, *rell, *ctxh, *ctxl;
    float* rowsum;
    cudaGetSymbolAddress((void**)&wqh, g_wqh);   cudaGetSymbolAddress((void**)&wql, g_wql);
    cudaGetSymbolAddress((void**)&wkh, g_wkh);   cudaGetSymbolAddress((void**)&wkl, g_wkl);
    cudaGetSymbolAddress((void**)&wvh, g_wvh);   cudaGetSymbolAddress((void**)&wvl, g_wvl);
    cudaGetSymbolAddress((void**)&woh, g_woh);   cudaGetSymbolAddress((void**)&wol, g_wol);
    cudaGetSymbolAddress((void**)&qh, g_qh);     cudaGetSymbolAddress((void**)&ql, g_ql);
    cudaGetSymbolAddress((void**)&kh, g_kh);     cudaGetSymbolAddress((void**)&kl, g_kl);
    cudaGetSymbolAddress((void**)&vh, g_vh);     cudaGetSymbolAddress((void**)&vl, g_vl);
    cudaGetSymbolAddress((void**)&relh, g_relh); cudaGetSymbolAddress((void**)&rell, g_rell);
    cudaGetSymbolAddress((void**)&ctxh, g_ctxh); cudaGetSymbolAddress((void**)&ctxl, g_ctxl);
    cudaGetSymbolAddress((void**)&rowsum, g_rowsum);

    cudaFuncSetAttribute(proj_qkv_mma, cudaFuncAttributeMaxDynamicSharedMemorySize, PROJ_SMEM);
    cudaFuncSetAttribute(outproj_mma,  cudaFuncAttributeMaxDynamicSharedMemorySize, 131072);
    cudaFuncSetAttribute(scores_fused, cudaFuncAttributeMaxDynamicSharedMemorySize, SMEM_SCORES);
    cudaFuncSetAttribute(ctx_mma,      cudaFuncAttributeMaxDynamicSharedMemorySize, CTX_SMEM);

    split_w<<<1024, 256>>>(Wq, Wk, Wv, Wo,
        wqh, wql, wkh, wkl, wvh, wvl, woh, wol);
    rel_proj_kernel<<<512, 256>>>(pos_emb, Wp, bp, relh, rell);

    proj_qkv_mma<<<dim3(4, 32, 3), 256, PROJ_SMEM>>>(query, key, value,
        wqh, wql, wkh, wkl, wvh, wvl, bq, bk, bv, qh, ql, kh, kl, vh, vl);

    scores_fused<<<dim3(8, 32), 512, SMEM_SCORES>>>(qh, ql, kh, kl, relh, rell,
                                                    csc, psc, attn, rowsum);
    ctx_mma<<<dim3(8, 32), 512, CTX_SMEM>>>(attn, vh, vl, rowsum, ctxh, ctxl);
    outproj_mma<<<dim3(4, 32), 256, 131072>>>(ctxh, ctxl, woh, wol, bo, out);
}

// round 15
// speedup vs baseline: 1.0713x; 1.0713x over previous
#include <cuda_runtime.h>
#include <cuda_bf16.h>
#include <cstdint>

#define Bb 4
#define Ss 1024
#define Dd 512
#define Hh 8
#define DH 64
#define RR 2047
#define RPAD 2304

__device__ __nv_bfloat16 g_inqh[4096*512], g_inql[4096*512];
__device__ __nv_bfloat16 g_inkh[4096*512], g_inkl[4096*512];
__device__ __nv_bfloat16 g_invh[4096*512], g_invl[4096*512];
__device__ __nv_bfloat16 g_wqh[512*512], g_wql[512*512];
__device__ __nv_bfloat16 g_wkh[512*512], g_wkl[512*512];
__device__ __nv_bfloat16 g_wvh[512*512], g_wvl[512*512];
__device__ __nv_bfloat16 g_woh[512*512], g_wol[512*512];
__device__ __nv_bfloat16 g_qh[32*1024*64], g_ql[32*1024*64];
__device__ __nv_bfloat16 g_kh[32*1024*64], g_kl[32*1024*64];
__device__ __nv_bfloat16 g_vh[32*1024*64], g_vl[32*1024*64];
__device__ __nv_bfloat16 g_relh[RPAD*64], g_rell[RPAD*64];
__device__ __nv_bfloat16 g_ctxh[4096*512], g_ctxl[4096*512];
__device__ float         g_rowsum[32*1024];

extern __shared__ char dsm[];

__device__ __forceinline__ uint32_t smem_u32(const void* p) {
    uint32_t a;
    asm("{ .reg .u64 t; cvta.to.shared.u64 t, %1; cvt.u32.u64 %0, t; }" : "=r"(a) : "l"(p));
    return a;
}
__device__ __forceinline__ void ldsm4(uint32_t* r, uint32_t a) {
    asm volatile("ldmatrix.sync.aligned.m8n8.x4.shared.b16 {%0,%1,%2,%3}, [%4];"
        : "=r"(r[0]), "=r"(r[1]), "=r"(r[2]), "=r"(r[3]) : "r"(a));
}
__device__ __forceinline__ void ldsm4t(uint32_t* r, uint32_t a) {
    asm volatile("ldmatrix.sync.aligned.m8n8.x4.trans.shared.b16 {%0,%1,%2,%3}, [%4];"
        : "=r"(r[0]), "=r"(r[1]), "=r"(r[2]), "=r"(r[3]) : "r"(a));
}
__device__ __forceinline__ void mma16816(float* d, const uint32_t* a, const uint32_t* b) {
    asm volatile("mma.sync.aligned.m16n8k16.row.col.f32.bf16.bf16.f32 "
        "{%0,%1,%2,%3}, {%4,%5,%6,%7}, {%8,%9}, {%0,%1,%2,%3};"
        : "+f"(d[0]), "+f"(d[1]), "+f"(d[2]), "+f"(d[3])
        : "r"(a[0]), "r"(a[1]), "r"(a[2]), "r"(a[3]), "r"(b[0]), "r"(b[1]));
}
__device__ __forceinline__ void cp16(uint32_t dst, const void* src) {
    asm volatile("cp.async.cg.shared.global [%0], [%1], 16;" :: "r"(dst), "l"(src));
}
#define CP_COMMIT() asm volatile("cp.async.commit_group;" ::: "memory")
#define CP_WAIT(N)  asm volatile("cp.async.wait_group %0;" :: "n"(N) : "memory")

__device__ __forceinline__ uint32_t pack_split(float a, float b, float& ra, float& rb) {
    __nv_bfloat16 ha = __float2bfloat16_rn(a), hb = __float2bfloat16_rn(b);
    ra = a - __bfloat162float(ha);
    rb = b - __bfloat162float(hb);
    return (uint32_t)__bfloat16_as_ushort(ha) | ((uint32_t)__bfloat16_as_ushort(hb) << 16);
}
__device__ __forceinline__ uint32_t pack_bf2(float a, float b) {
    return (uint32_t)__bfloat16_as_ushort(__float2bfloat16_rn(a)) |
           ((uint32_t)__bfloat16_as_ushort(__float2bfloat16_rn(b)) << 16);
}

// ---------- merged 7-tensor fp32 -> bf16 hi/lo split (one launch) ---------
__global__ __launch_bounds__(256)
void split_all(const float* q, const float* k, const float* v,
               const float* Wq, const float* Wk, const float* Wv, const float* Wo,
               __nv_bfloat16* qhh, __nv_bfloat16* qll, __nv_bfloat16* khh, __nv_bfloat16* kll,
               __nv_bfloat16* vhh, __nv_bfloat16* vll,
               __nv_bfloat16* wqh, __nv_bfloat16* wql, __nv_bfloat16* wkh, __nv_bfloat16* wkl,
               __nv_bfloat16* wvh, __nv_bfloat16* wvl, __nv_bfloat16* woh, __nv_bfloat16* wol) {
    int gb = blockIdx.x;
    const float* in; __nv_bfloat16 *oh, *ol; int i;
    if (gb < 6144) {
        int w = gb >> 11; i = (gb & 2047) * 256 + threadIdx.x;
        in = w == 0 ? q : w == 1 ? k : v;
        oh = w == 0 ? qhh : w == 1 ? khh : vhh;
        ol = w == 0 ? qll : w == 1 ? kll : vll;
    } else {
        int w = (gb - 6144) >> 8; i = ((gb - 6144) & 255) * 256 + threadIdx.x;
        in = w == 0 ? Wq : w == 1 ? Wk : w == 2 ? Wv : Wo;
        oh = w == 0 ? wqh : w == 1 ? wkh : w == 2 ? wvh : woh;
        ol = w == 0 ? wql : w == 1 ? wkl : w == 2 ? wvl : wol;
    }
    float4 val = reinterpret_cast<const float4*>(in)[i];
    float r0, r1, r2, r3;
    uint32_t h0 = pack_split(val.x, val.y, r0, r1);
    uint32_t h1 = pack_split(val.z, val.w, r2, r3);
    reinterpret_cast<uint2*>(oh)[i] = make_uint2(h0, h1);
    reinterpret_cast<uint2*>(ol)[i] = make_uint2(pack_bf2(r0, r1), pack_bf2(r2, r3));
}

// ---- shared 48-MMA step, per-j B loads (low register pressure) -----------
__device__ __forceinline__ void mma_step48(float acc[2][8][4], uint32_t aBase, uint32_t bBase,
                                           uint32_t a_off, uint32_t a_sw, uint32_t a_cb,
                                           uint32_t b_off, uint32_t b_sw, uint32_t b_cb) {
    #pragma unroll
    for (int k = 0; k < 4; k++) {
        uint32_t aA = aBase + a_off + (((uint32_t)(k * 32) + a_cb) ^ a_sw);
        uint32_t ah0[4], ah1[4], al0[4], al1[4];
        ldsm4(ah0, aA); ldsm4(ah1, aA + 2048);
        ldsm4(al0, aA + 16384); ldsm4(al1, aA + 16384 + 2048);
        uint32_t bA = bBase + b_off + (((uint32_t)(k * 32) + b_cb) ^ b_sw);
        #pragma unroll
        for (int j = 0; j < 4; j++) {
            uint32_t bh[4], bl[4];
            ldsm4(bh, bA + j * 2048); ldsm4(bl, bA + 16384 + j * 2048);
            mma16816(acc[0][2*j],   ah0, &bh[0]); mma16816(acc[0][2*j+1], ah0, &bh[2]);
            mma16816(acc[1][2*j],   ah1, &bh[0]); mma16816(acc[1][2*j+1], ah1, &bh[2]);
            mma16816(acc[0][2*j],   ah0, &bl[0]); mma16816(acc[0][2*j+1], ah0, &bl[2]);
            mma16816(acc[1][2*j],   ah1, &bl[0]); mma16816(acc[1][2*j+1], ah1, &bl[2]);
            mma16816(acc[0][2*j],   al0, &bh[0]); mma16816(acc[0][2*j+1], al0, &bh[2]);
            mma16816(acc[1][2*j],   al1, &bh[0]); mma16816(acc[1][2*j+1], al1, &bh[2]);
        }
    }
}

// ====== K-chunked 128x128 GEMM: A single-buffer, B double-buffer (96KB) ===
// smem: A hi 0(16K), A lo 16384(16K); B ring 32768 + st*32768 (hi 16K, lo 16K)
__device__ __forceinline__ void mma_core_128(
    float acc[2][8][4],
    const __nv_bfloat16* Ah, const __nv_bfloat16* Al, int lda,
    const __nv_bfloat16* Bh, const __nv_bfloat16* Bl, int ldb, int kchunks)
{
    const uint32_t sb = smem_u32(dsm);
    int tid = threadIdx.x, lane = tid & 31, wid = tid >> 5;
    int wm = (wid & 3) << 5, wn = (wid >> 2) << 6;
    uint32_t a_row = wm + (lane & 15);
    uint32_t a_off = a_row * 128, a_sw = (a_row & 7) << 4, a_cb = lane & 16;
    uint32_t b_row = wn + (lane & 7) + ((lane >> 1) & 8);
    uint32_t b_off = b_row * 128, b_sw = (b_row & 7) << 4, b_cb = (lane & 8) << 1;

    auto issueA = [&](int kc) {
        #pragma unroll
        for (int l = 0; l < 4; l++) {
            int i = tid + l * 256, r = i >> 3, c = i & 7;
            uint32_t doff = r * 128 + ((c * 16) ^ ((r & 7) << 4));
            size_t ga = (size_t)r * lda + kc * 64 + c * 8;
            cp16(sb + doff, Ah + ga);
            cp16(sb + 16384 + doff, Al + ga);
        }
        CP_COMMIT();
    };
    auto issueB = [&](int kc, int st) {
        uint32_t s0 = sb + 32768 + (uint32_t)st * 32768u;
        #pragma unroll
        for (int l = 0; l < 4; l++) {
            int i = tid + l * 256, r = i >> 3, c = i & 7;
            uint32_t doff = r * 128 + ((c * 16) ^ ((r & 7) << 4));
            size_t gb = (size_t)r * ldb + kc * 64 + c * 8;
            cp16(s0 + doff, Bh + gb);
            cp16(s0 + 16384 + doff, Bl + gb);
        }
        CP_COMMIT();
    };

    issueA(0); issueB(0, 0);
    for (int kc = 0; kc < kchunks; kc++) {
        if (kc + 1 < kchunks) { issueB(kc + 1, (kc + 1) & 1); CP_WAIT(1); }
        else CP_WAIT(0);
        __syncthreads();
        mma_step48(acc, sb, sb + 32768 + (uint32_t)(kc & 1) * 32768u,
                   a_off, a_sw, a_cb, b_off, b_sw, b_cb);
        __syncthreads();
        if (kc + 1 < kchunks) issueA(kc + 1);
    }
}

// ===== MEGA scores: 128-row blocks, 512 threads, 4x4 warp grid ===========
#define PS_OFF 65536
#define RS_OFF (PS_OFF + 133120)
#define SMEM_SCORES (RS_OFF + 64)

__global__ __launch_bounds__(512)
void scores_fused(const __nv_bfloat16* qh_g, const __nv_bfloat16* ql_g,
                  const __nv_bfloat16* kh_g, const __nv_bfloat16* kl_g,
                  const __nv_bfloat16* relh, const __nv_bfloat16* rell,
                  float* __restrict__ csc, float* __restrict__ psc,
                  float* __restrict__ eb, float* __restrict__ rowsum_g)
{
    const uint32_t sb = smem_u32(dsm);
    float* p_sh = reinterpret_cast<float*>(dsm + PS_OFF);     // [128][260]
    int tid = threadIdx.x, lane = tid & 31, wid = tid >> 5;
    int wm = (wid & 3) << 5, wn = (wid >> 2) << 5;            // 4x4 grid, 32x32 tiles
    int sblk = blockIdx.x, bh = blockIdx.y, s0 = sblk << 7;

    uint32_t a_row = wm + (lane & 15);
    uint32_t a_off = a_row * 128, a_sw = (a_row & 7) << 4, a_cb = lane & 16;
    uint32_t b_row = wn + (lane & 7) + ((lane >> 1) & 8);
    uint32_t b_off = b_row * 128, b_sw = (b_row & 7) << 4, b_cb = (lane & 8) << 1;

    const __nv_bfloat16* qhb = qh_g + ((size_t)bh * Ss + s0) * DH;
    const __nv_bfloat16* qlb = ql_g + ((size_t)bh * Ss + s0) * DH;
    const __nv_bfloat16* khb = kh_g + (size_t)bh * Ss * DH;
    const __nv_bfloat16* klb = kl_g + (size_t)bh * Ss * DH;

    #pragma unroll
    for (int l = 0; l < 2; l++) {
        int i = tid + l * 512, r = i >> 3, c = i & 7;
        uint32_t doff = r * 128 + ((c * 16) ^ ((r & 7) << 4));
        cp16(sb + doff, qhb + (size_t)r * 64 + c * 8);
        cp16(sb + 16384 + doff, qlb + (size_t)r * 64 + c * 8);
    }
    auto loadB = [&](const __nv_bfloat16* BH, const __nv_bfloat16* BL) {
        #pragma unroll
        for (int l = 0; l < 2; l++) {
            int i = tid + l * 512, r = i >> 3, c = i & 7;
            uint32_t doff = r * 128 + ((c * 16) ^ ((r & 7) << 4));
            cp16(sb + 32768 + doff, BH + (size_t)r * 64 + c * 8);
            cp16(sb + 49152 + doff, BL + (size_t)r * 64 + c * 8);
        }
        CP_COMMIT();
    };

    float acc[2][4][4];
    auto gemm = [&]() {
        #pragma unroll
        for (int mi = 0; mi < 2; mi++)
            #pragma unroll
            for (int jj = 0; jj < 4; jj++)
                #pragma unroll
                for (int x = 0; x < 4; x++) acc[mi][jj][x] = 0.f;
        #pragma unroll
        for (int k = 0; k < 4; k++) {
            uint32_t aA = sb + a_off + (((uint32_t)(k * 32) + a_cb) ^ a_sw);
            uint32_t ah0[4], ah1[4], al0[4], al1[4];
            ldsm4(ah0, aA); ldsm4(ah1, aA + 2048);
            ldsm4(al0, aA + 16384); ldsm4(al1, aA + 16384 + 2048);
            uint32_t bA = sb + 32768 + b_off + (((uint32_t)(k * 32) + b_cb) ^ b_sw);
            #pragma unroll
            for (int jb = 0; jb < 2; jb++) {
                uint32_t bh4[4], bl4[4];
                ldsm4(bh4, bA + jb * 2048);
                ldsm4(bl4, bA + 16384 + jb * 2048);
                #pragma unroll
                for (int h = 0; h < 2; h++) {
                    int jj = jb * 2 + h;
                    mma16816(acc[0][jj], ah0, &bh4[2*h]); mma16816(acc[1][jj], ah1, &bh4[2*h]);
                    mma16816(acc[0][jj], ah0, &bl4[2*h]); mma16816(acc[1][jj], ah1, &bl4[2*h]);
                    mma16816(acc[0][jj], al0, &bh4[2*h]); mma16816(acc[1][jj], al1, &bh4[2*h]);
                }
            }
        }
    };

    int er_ = wm + (lane >> 2), ec_ = wn + ((lane & 3) << 1);

    auto scatter = [&](int ju) {
        #pragma unroll
        for (int mi = 0; mi < 2; mi++)
            #pragma unroll
            for (int jj = 0; jj < 4; jj++) {
                int u = ju * 128 + ec_ + jj * 8;
                #pragma unroll
                for (int hf = 0; hf < 2; hf++) {
                    int r = er_ + mi * 16 + hf * 8;
                    int t = u + r - 127;
                    if ((unsigned)t < 1024u)       p_sh[r * 260 + (t & 255)] = acc[mi][jj][hf * 2];
                    if ((unsigned)(t + 1) < 1024u) p_sh[r * 260 + ((t + 1) & 255)] = acc[mi][jj][hf * 2 + 1];
                }
            }
    };

    int relbase = 896 - s0;
    loadB(relh + (size_t)relbase * 64, rell + (size_t)relbase * 64);
    CP_WAIT(0); __syncthreads();
    gemm();                                     // pos u-tile 0
    __syncthreads();
    loadB(relh + (size_t)(relbase + 128) * 64, rell + (size_t)(relbase + 128) * 64);
    scatter(0);
    CP_WAIT(0); __syncthreads();

    const float scl = 0.04419417382415922f;
    size_t prow = (size_t)bh * Ss + s0;
    float rs[4] = {0.f, 0.f, 0.f, 0.f};

    for (int j = 0; j < 8; j++) {
        gemm();                                 // pos u-tile j+1
        __syncthreads();
        loadB(khb + (size_t)(j * 128) * 64, klb + (size_t)(j * 128) * 64);
        scatter(j + 1);
        CP_WAIT(0); __syncthreads();
        gemm();                                 // content tile j
        __syncthreads();                        // B consumed
        if (j < 7) {
            int rb = relbase + (j + 2) * 128;
            loadB(relh + (size_t)rb * 64, rell + (size_t)rb * 64);   // overlap epilogue
        }
        #pragma unroll
        for (int l = 0; l < 8; l++) {           // coalesced psc tile write
            int i = tid + l * 512, r = i >> 5, c4 = i & 31;
            float4 v = *reinterpret_cast<float4*>(&p_sh[r * 260 + ((j & 1) * 128) + c4 * 4]);
            *reinterpret_cast<float4*>(&psc[(prow + r) * Ss + j * 128 + c4 * 4]) = v;
        }
        #pragma unroll
        for (int mi = 0; mi < 2; mi++)
            #pragma unroll
            for (int jj = 0; jj < 4; jj++) {
                int tb = j * 128 + ec_ + jj * 8;
                int sc = (j & 1) * 128 + ((ec_ + jj * 8) & 127);
                int r0 = er_ + mi * 16, r1 = r0 + 8;
                float2 p0 = *reinterpret_cast<float2*>(&p_sh[r0 * 260 + sc]);
                float2 p1 = *reinterpret_cast<float2*>(&p_sh[r1 * 260 + sc]);
                float c0 = acc[mi][jj][0], c1 = acc[mi][jj][1];
                float c2 = acc[mi][jj][2], c3 = acc[mi][jj][3];
                size_t o0 = (prow + r0) * Ss + tb, o1 = (prow + r1) * Ss + tb;
                *reinterpret_cast<float2*>(&csc[o0]) = make_float2(c0, c1);
                *reinterpret_cast<float2*>(&csc[o1]) = make_float2(c2, c3);
                float e00 = __expf((c0 + p0.x) * scl), e01 = __expf((c1 + p0.y) * scl);
                float e10 = __expf((c2 + p1.x) * scl), e11 = __expf((c3 + p1.y) * scl);
                *reinterpret_cast<float2*>(&eb[o0]) = make_float2(e00, e01);
                *reinterpret_cast<float2*>(&eb[o1]) = make_float2(e10, e11);
                rs[mi * 2 + 0] += e00 + e01;
                rs[mi * 2 + 1] += e10 + e11;
            }
        CP_WAIT(0); __syncthreads();
    }

    #pragma unroll
    for (int i = 0; i < 4; i++) {
        rs[i] += __shfl_xor_sync(~0u, rs[i], 1);
        rs[i] += __shfl_xor_sync(~0u, rs[i], 2);
    }
    float* rsh = reinterpret_cast<float*>(dsm + 32768);   // [4 groups][128]
    if ((lane & 3) == 0) {
        int g = wid >> 2;
        rsh[g * 128 + er_]      = rs[0];
        rsh[g * 128 + er_ + 8]  = rs[1];
        rsh[g * 128 + er_ + 16] = rs[2];
        rsh[g * 128 + er_ + 24] = rs[3];
    }
    __syncthreads();
    if (tid < 128)
        rowsum_g[prow + tid] = (rsh[tid] + rsh[128 + tid]) + (rsh[256 + tid] + rsh[384 + tid]);
}

// ------ q/k/v projection, z-indexed single launch (96KB, 2 CTAs/SM) -------
__global__ __launch_bounds__(256, 2)
void proj_qkv_mma(const __nv_bfloat16* xqh, const __nv_bfloat16* xql,
                  const __nv_bfloat16* xkh, const __nv_bfloat16* xkl,
                  const __nv_bfloat16* xvh, const __nv_bfloat16* xvl,
                  const __nv_bfloat16* wqh, const __nv_bfloat16* wql,
                  const __nv_bfloat16* wkh, const __nv_bfloat16* wkl,
                  const __nv_bfloat16* wvh, const __nv_bfloat16* wvl,
                  const float* bq, const float* bk, const float* bv,
                  __nv_bfloat16* qh, __nv_bfloat16* ql, __nv_bfloat16* kh,
                  __nv_bfloat16* kl, __nv_bfloat16* vh, __nv_bfloat16* vl) {
    int z = blockIdx.z;
    const __nv_bfloat16* xh = z == 0 ? xqh : z == 1 ? xkh : xvh;
    const __nv_bfloat16* xl = z == 0 ? xql : z == 1 ? xkl : xvl;
    const __nv_bfloat16* wh = z == 0 ? wqh : z == 1 ? wkh : wvh;
    const __nv_bfloat16* wl = z == 0 ? wql : z == 1 ? wkl : wvl;
    const float* bias = z == 0 ? bq : z == 1 ? bk : bv;
    __nv_bfloat16* oh = z == 0 ? qh : z == 1 ? kh : vh;
    __nv_bfloat16* ol = z == 0 ? ql : z == 1 ? kl : vl;

    int n0 = blockIdx.x << 7, m0 = blockIdx.y << 7;
    float acc[2][8][4] = {};
    mma_core_128(acc, xh + (size_t)m0 * Dd, xl + (size_t)m0 * Dd, Dd,
                 wh + (size_t)n0 * Dd, wl + (size_t)n0 * Dd, Dd, 8);
    int lane = threadIdx.x & 31, wid = threadIdx.x >> 5;
    int er = ((wid & 3) << 5) + (lane >> 2);
    int ec = ((wid >> 2) << 6) + ((lane & 3) << 1);
    #pragma unroll
    for (int mi = 0; mi < 2; mi++)
        #pragma unroll
        for (int j = 0; j < 8; j++) {
            int c = n0 + ec + j * 8;
            float b0 = bias[c], b1 = bias[c + 1];
            #pragma unroll
            for (int hf = 0; hf < 2; hf++) {
                int m = m0 + er + mi * 16 + hf * 8;
                float v0 = acc[mi][j][hf*2] + b0, v1 = acc[mi][j][hf*2+1] + b1;
                int b = m >> 10, s = m & 1023, h = c >> 6, d = c & 63;
                size_t off = ((size_t)((((b << 3) | h) << 10) | s)) * DH + d;
                float r0, r1;
                uint32_t hv = pack_split(v0, v1, r0, r1);
                *reinterpret_cast<uint32_t*>(&oh[off]) = hv;
                *reinterpret_cast<uint32_t*>(&ol[off]) = pack_bf2(r0, r1);
            }
        }
}

// ------ output projection (96KB, 2 CTAs/SM) --------------------------------
__global__ __launch_bounds__(256, 2)
void outproj_mma(const __nv_bfloat16* xh, const __nv_bfloat16* xl,
                 const __nv_bfloat16* wh, const __nv_bfloat16* wl,
                 const float* bias, float* __restrict__ out) {
    int n0 = blockIdx.x << 7, m0 = blockIdx.y << 7;
    float acc[2][8][4] = {};
    mma_core_128(acc, xh + (size_t)m0 * Dd, xl + (size_t)m0 * Dd, Dd,
                 wh + (size_t)n0 * Dd, wl + (size_t)n0 * Dd, Dd, 8);
    int lane = threadIdx.x & 31, wid = threadIdx.x >> 5;
    int er = ((wid & 3) << 5) + (lane >> 2);
    int ec = ((wid >> 2) << 6) + ((lane & 3) << 1);
    #pragma unroll
    for (int mi = 0; mi < 2; mi++)
        #pragma unroll
        for (int j = 0; j < 8; j++) {
            int c = n0 + ec + j * 8;
            float b0 = bias[c], b1 = bias[c + 1];
            int m = m0 + er + mi * 16;
            *reinterpret_cast<float2*>(&out[(size_t)m * Dd + c]) =
                make_float2(acc[mi][j][0] + b0, acc[mi][j][1] + b1);
            *reinterpret_cast<float2*>(&out[(size_t)(m + 8) * Dd + c]) =
                make_float2(acc[mi][j][2] + b0, acc[mi][j][3] + b1);
        }
}

// ---------------- rel projection ------------------------------------------
__global__ __launch_bounds__(256)
void rel_proj_kernel(const float* P, const float* Wp, const float* bp,
                     __nv_bfloat16* oh, __nv_bfloat16* ol) {
    __shared__ float sWT[64 * 64];
    __shared__ float sP[4][64];
    int tid = threadIdx.x;
    for (int i = tid; i < 4096; i += 256) sWT[(i & 63) * 64 + (i >> 6)] = Wp[i];
    int g = tid >> 6, d = tid & 63;
    int r = blockIdx.x * 4 + g;
    sP[g][d] = (r < RR) ? P[r * 64 + d] : 0.f;
    __syncthreads();
    float acc = bp[d];
    #pragma unroll 16
    for (int c = 0; c < 64; c++) acc += sP[g][c] * sWT[c * 64 + d];
    if (r < RR) {
        __nv_bfloat16 h = __float2bfloat16_rn(acc);
        oh[r * 64 + d] = h;
        ol[r * 64 + d] = __float2bfloat16_rn(acc - __bfloat162float(h));
    }
}

// ------ ctx: 512 threads, V double-buffered; normalizes e, rewrites attn --
#define CTX_SMEM 65536

__global__ __launch_bounds__(512)
void ctx_mma(float* __restrict__ attn, const __nv_bfloat16* vh, const __nv_bfloat16* vl,
             const float* __restrict__ rowsum_g, __nv_bfloat16* ch, __nv_bfloat16* cl) {
    char* sAh = dsm; char* sAl = dsm + 16384;
    const uint32_t sb = smem_u32(dsm);
    __shared__ float sinv[128];
    int bh = blockIdx.y, s0 = blockIdx.x << 7;
    float* ab = attn + ((size_t)bh * Ss + s0) * Ss;
    const __nv_bfloat16* vhb = vh + (size_t)bh * Ss * DH;
    const __nv_bfloat16* vlb = vl + (size_t)bh * Ss * DH;
    int tid = threadIdx.x, lane = tid & 31, wid = tid >> 5;
    int wm = (wid & 3) << 5, wn = (wid >> 2) << 4;       // 4x4 warps, 32x16 tiles

    if (tid < 128) sinv[tid] = 1.0f / rowsum_g[(size_t)bh * Ss + s0 + tid];
    __syncthreads();

    uint32_t a_row = wm + (lane & 15);
    uint32_t a_off = a_row * 128, a_sw = (a_row & 7) << 4, a_cb = lane & 16;
    uint32_t bt = (lane & 7) + (lane & 8);
    uint32_t vcb = (uint32_t)(wn * 2) + (lane & 16);

    auto loadV = [&](int kc) {
        uint32_t vb = sb + 32768 + (uint32_t)(kc & 1) * 16384;
        int r = tid >> 3, c = tid & 7;
        uint32_t doff = r * 128 + ((c * 16) ^ ((r & 7) << 4));
        size_t g = (size_t)(kc * 64 + r) * DH + c * 8;
        cp16(vb + doff, vhb + g);
        cp16(vb + 8192 + doff, vlb + g);
        CP_COMMIT();
    };

    loadV(0);
    float acc[2][2][4] = {};
    for (int kc = 0; kc < 16; kc++) {
        if (kc) __syncthreads();
        if (kc + 1 < 16) loadV(kc + 1);
        #pragma unroll
        for (int l = 0; l < 4; l++) {
            int i = tid + l * 512, r = i >> 4, c = i & 15;
            float iv = sinv[r];
            float* gp = ab + (size_t)r * Ss + kc * 64 + c * 4;
            float4 v = *reinterpret_cast<const float4*>(gp);
            v.x *= iv; v.y *= iv; v.z *= iv; v.w *= iv;
            *reinterpret_cast<float4*>(gp) = v;
            float r0, r1, r2, r3;
            uint32_t h0 = pack_split(v.x, v.y, r0, r1);
            uint32_t h1 = pack_split(v.z, v.w, r2, r3);
            uint32_t doff = r * 128 + ((c * 8) ^ ((r & 7) << 4));
            *reinterpret_cast<uint2*>(sAh + doff) = make_uint2(h0, h1);
            *reinterpret_cast<uint2*>(sAl + doff) = make_uint2(pack_bf2(r0, r1), pack_bf2(r2, r3));
        }
        if (kc + 1 < 16) CP_WAIT(1); else CP_WAIT(0);
        __syncthreads();
        uint32_t vb = sb + 32768 + (uint32_t)(kc & 1) * 16384;
        #pragma unroll
        for (int k = 0; k < 4; k++) {
            uint32_t aA = sb + a_off + (((uint32_t)(k * 32) + a_cb) ^ a_sw);
            uint32_t ah0[4], ah1[4], al0[4], al1[4];
            ldsm4(ah0, aA); ldsm4(ah1, aA + 2048);
            ldsm4(al0, aA + 16384); ldsm4(al1, aA + 16384 + 2048);
            uint32_t t = (uint32_t)(k * 16) + bt;
            uint32_t va = vb + t * 128 + (vcb ^ ((t & 7) << 4));
            uint32_t vhf[4], vlf[4];
            ldsm4t(vhf, va);
            ldsm4t(vlf, va + 8192);
            #pragma unroll
            for (int jj = 0; jj < 2; jj++) {
                const uint32_t* bhp = &vhf[jj * 2];
                const uint32_t* blp = &vlf[jj * 2];
                mma16816(acc[0][jj], ah0, bhp); mma16816(acc[1][jj], ah1, bhp);
                mma16816(acc[0][jj], ah0, blp); mma16816(acc[1][jj], ah1, blp);
                mma16816(acc[0][jj], al0, bhp); mma16816(acc[1][jj], al1, bhp);
            }
        }
    }
    int b = bh >> 3, h = bh & 7;
    int er = wm + (lane >> 2), ec = wn + ((lane & 3) << 1);
    #pragma unroll
    for (int mi = 0; mi < 2; mi++)
        #pragma unroll
        for (int jj = 0; jj < 2; jj++)
            #pragma unroll
            for (int hf = 0; hf < 2; hf++) {
                int s = s0 + er + mi * 16 + hf * 8;
                int d = ec + jj * 8;
                size_t off = ((size_t)((b << 10) | s)) * Dd + (h << 6) + d;
                float r0, r1;
                uint32_t hv = pack_split(acc[mi][jj][hf*2], acc[mi][jj][hf*2+1], r0, r1);
                *reinterpret_cast<uint32_t*>(&ch[off]) = hv;
                *reinterpret_cast<uint32_t*>(&cl[off]) = pack_bf2(r0, r1);
            }
}

// -------------------------------------------------------------------------
extern "C" void kernel_launch(void* const* d_in, const int* in_sizes, int n_in,
                              void* d_out, int out_size) {
    const float* query   = (const float*)d_in[0];
    const float* key     = (const float*)d_in[1];
    const float* value   = (const float*)d_in[2];
    const float* pos_emb = (const float*)d_in[3];
    const float *Wq = (const float*)d_in[4],  *bq = (const float*)d_in[5];
    const float *Wk = (const float*)d_in[6],  *bk = (const float*)d_in[7];
    const float *Wv = (const float*)d_in[8],  *bv = (const float*)d_in[9];
    const float *Wo = (const float*)d_in[10], *bo = (const float*)d_in[11];
    const float *Wp = (const float*)d_in[12], *bp = (const float*)d_in[13];

    float* out  = (float*)d_out;
    float* attn = out  + (size_t)Bb * Ss * Dd;
    float* csc  = attn + (size_t)Bb * Hh * Ss * Ss;
    float* psc  = csc  + (size_t)Bb * Hh * Ss * Ss;

    __nv_bfloat16 *inqh, *inql, *inkh, *inkl, *invh, *invl;
    __nv_bfloat16 *wqh, *wql, *wkh, *wkl, *wvh, *wvl, *woh, *wol;
    __nv_bfloat16 *qh, *ql, *kh, *kl, *vh, *vl, *relh, *rell, *ctxh, *ctxl;
    float* rowsum;
    cudaGetSymbolAddress((void**)&inqh, g_inqh); cudaGetSymbolAddress((void**)&inql, g_inql);
    cudaGetSymbolAddress((void**)&inkh, g_inkh); cudaGetSymbolAddress((void**)&inkl, g_inkl);
    cudaGetSymbolAddress((void**)&invh, g_invh); cudaGetSymbolAddress((void**)&invl, g_invl);
    cudaGetSymbolAddress((void**)&wqh, g_wqh);   cudaGetSymbolAddress((void**)&wql, g_wql);
    cudaGetSymbolAddress((void**)&wkh, g_wkh);   cudaGetSymbolAddress((void**)&wkl, g_wkl);
    cudaGetSymbolAddress((void**)&wvh, g_wvh);   cudaGetSymbolAddress((void**)&wvl, g_wvl);
    cudaGetSymbolAddress((void**)&woh, g_woh);   cudaGetSymbolAddress((void**)&wol, g_wol);
    cudaGetSymbolAddress((void**)&qh, g_qh);     cudaGetSymbolAddress((void**)&ql, g_ql);
    cudaGetSymbolAddress((void**)&kh, g_kh);     cudaGetSymbolAddress((void**)&kl, g_kl);
    cudaGetSymbolAddress((void**)&vh, g_vh);     cudaGetSymbolAddress((void**)&vl, g_vl);
    cudaGetSymbolAddress((void**)&relh, g_relh); cudaGetSymbolAddress((void**)&rell, g_rell);
    cudaGetSymbolAddress((void**)&ctxh, g_ctxh); cudaGetSymbolAddress((void**)&ctxl, g_ctxl);
    cudaGetSymbolAddress((void**)&rowsum, g_rowsum);

    cudaFuncSetAttribute(proj_qkv_mma, cudaFuncAttributeMaxDynamicSharedMemorySize, 98304);
    cudaFuncSetAttribute(outproj_mma,  cudaFuncAttributeMaxDynamicSharedMemorySize, 98304);
    cudaFuncSetAttribute(scores_fused, cudaFuncAttributeMaxDynamicSharedMemorySize, SMEM_SCORES);
    cudaFuncSetAttribute(ctx_mma,      cudaFuncAttributeMaxDynamicSharedMemorySize, CTX_SMEM);

    split_all<<<7168, 256>>>(query, key, value, Wq, Wk, Wv, Wo,
        inqh, inql, inkh, inkl, invh, invl,
        wqh, wql, wkh, wkl, wvh, wvl, woh, wol);
    rel_proj_kernel<<<512, 256>>>(pos_emb, Wp, bp, relh, rell);

    proj_qkv_mma<<<dim3(4, 32, 3), 256, 98304>>>(inqh, inql, inkh, inkl, invh, invl,
        wqh, wql, wkh, wkl, wvh, wvl, bq, bk, bv, qh, ql, kh, kl, vh, vl);

    scores_fused<<<dim3(8, 32), 512, SMEM_SCORES>>>(qh, ql, kh, kl, relh, rell,
                                                    csc, psc, attn, rowsum);
    ctx_mma<<<dim3(8, 32), 512, CTX_SMEM>>>(attn, vh, vl, rowsum, ctxh, ctxl);
    outproj_mma<<<dim3(4, 32), 256, 98304>>>(ctxh, ctxl, woh, wol, bo, out);
}